// round 8
// baseline (speedup 1.0000x reference)
#include <cuda_runtime.h>
#include <cuda_bf16.h>
#include <math.h>
#include <stdint.h>

// Problem constants
constexpr int Bsz = 2, Lsz = 2048, DM = 1024, DI = 2048, DS = 16, DR = 64;
constexpr int M = Bsz * Lsz;          // 4096
constexpr int XZ_N = 2 * DI;          // 4096
constexpr int DBC_LD = 128;           // padded dbc row stride (real cols: 96)
constexpr int NC = 32, LC = 64;       // scan chunking: 32 chunks x 64 steps
constexpr int NCH = Bsz * DI;         // 4096 channels

// fp32 scratch
__device__ float g_xz[(size_t)M * XZ_N];
__device__ float g_xc[(size_t)M * DI];
__device__ float g_dbcp[(size_t)M * DBC_LD];
__device__ float g_delta[(size_t)M * DI];
__device__ float g_yz[(size_t)M * DI];           // raw local scan y
// scan chunk state
__device__ float g_hend[(size_t)NC * NCH * DS];
__device__ float g_ptot[(size_t)NC * NCH * DS];
__device__ float g_hin [(size_t)NC * NCH * DS];
// bf16 split operands (A row-major [rows,K]; B stored K-major as [N,K])
__device__ __nv_bfloat16 g_xh[(size_t)M * DM],      g_xl[(size_t)M * DM];
__device__ __nv_bfloat16 g_winh[(size_t)XZ_N * DM], g_winl[(size_t)XZ_N * DM];
__device__ __nv_bfloat16 g_xch[(size_t)M * DI],     g_xcl[(size_t)M * DI];
__device__ __nv_bfloat16 g_wxh[(size_t)DBC_LD * DI], g_wxl[(size_t)DBC_LD * DI];
__device__ __nv_bfloat16 g_yzh[(size_t)M * DI],     g_yzl[(size_t)M * DI];
__device__ __nv_bfloat16 g_wouth[(size_t)DM * DI],  g_woutl[(size_t)DM * DI];

__device__ __forceinline__ float sigmoidf_fast(float x) {
    return 1.0f / (1.0f + __expf(-x));
}
__device__ __forceinline__ float softplusf(float x) {
    return (x > 20.0f) ? x : log1pf(expf(x));
}

// ---------------------------------------------------------------------------
// PTX helpers (portable sm_80+ PTX only)
// ---------------------------------------------------------------------------
__device__ __forceinline__ void cp_async16(uint32_t dst, const void* src) {
    asm volatile("cp.async.cg.shared.global [%0], [%1], 16;"
                 :: "r"(dst), "l"(src) : "memory");
}
__device__ __forceinline__ void cp_commit() {
    asm volatile("cp.async.commit_group;" ::: "memory");
}
template <int N>
__device__ __forceinline__ void cp_wait() {
    asm volatile("cp.async.wait_group %0;" :: "n"(N) : "memory");
}
__device__ __forceinline__ void ldsm_x4(uint32_t* r, uint32_t addr) {
    asm volatile("ldmatrix.sync.aligned.m8n8.x4.shared.b16 {%0,%1,%2,%3}, [%4];"
                 : "=r"(r[0]), "=r"(r[1]), "=r"(r[2]), "=r"(r[3]) : "r"(addr));
}
__device__ __forceinline__ void mma16816(float* c, const uint32_t* a,
                                         uint32_t b0, uint32_t b1) {
    asm volatile(
        "mma.sync.aligned.m16n8k16.row.col.f32.bf16.bf16.f32 "
        "{%0,%1,%2,%3}, {%4,%5,%6,%7}, {%8,%9}, {%0,%1,%2,%3};"
        : "+f"(c[0]), "+f"(c[1]), "+f"(c[2]), "+f"(c[3])
        : "r"(a[0]), "r"(a[1]), "r"(a[2]), "r"(a[3]), "r"(b0), "r"(b1));
}

// ---------------------------------------------------------------------------
// Split fp32 -> (hi, lo) bf16, same layout
// ---------------------------------------------------------------------------
__global__ void split_k(const float* __restrict__ in,
                        __nv_bfloat16* __restrict__ hi,
                        __nv_bfloat16* __restrict__ lo, int n4)
{
    int i = blockIdx.x * blockDim.x + threadIdx.x;
    if (i >= n4) return;
    float4 v = ((const float4*)in)[i];
    __nv_bfloat16 h0 = __float2bfloat16(v.x);
    __nv_bfloat16 h1 = __float2bfloat16(v.y);
    __nv_bfloat16 h2 = __float2bfloat16(v.z);
    __nv_bfloat16 h3 = __float2bfloat16(v.w);
    ushort4 hh, ll;
    hh.x = __bfloat16_as_ushort(h0); hh.y = __bfloat16_as_ushort(h1);
    hh.z = __bfloat16_as_ushort(h2); hh.w = __bfloat16_as_ushort(h3);
    ll.x = __bfloat16_as_ushort(__float2bfloat16(v.x - __bfloat162float(h0)));
    ll.y = __bfloat16_as_ushort(__float2bfloat16(v.y - __bfloat162float(h1)));
    ll.z = __bfloat16_as_ushort(__float2bfloat16(v.z - __bfloat162float(h2)));
    ll.w = __bfloat16_as_ushort(__float2bfloat16(v.w - __bfloat162float(h3)));
    ((ushort4*)hi)[i] = hh;
    ((ushort4*)lo)[i] = ll;
}

// ---------------------------------------------------------------------------
// Transpose + split: in [K,N] fp32 row-major -> hi/lo [N,K] bf16
// ---------------------------------------------------------------------------
__global__ void tsplit_k(const float* __restrict__ in, int Kdim, int Ndim,
                         __nv_bfloat16* __restrict__ hi,
                         __nv_bfloat16* __restrict__ lo)
{
    __shared__ float t[32][33];
    const int n0 = blockIdx.x * 32, k0 = blockIdx.y * 32;
    const int tx = threadIdx.x, ty = threadIdx.y;  // block (32, 8)
    for (int i = ty; i < 32; i += 8)
        t[i][tx] = in[(size_t)(k0 + i) * Ndim + n0 + tx];
    __syncthreads();
    for (int i = ty; i < 32; i += 8) {
        float v = t[tx][i];  // = in[k0+tx][n0+i]
        __nv_bfloat16 h = __float2bfloat16(v);
        hi[(size_t)(n0 + i) * Kdim + k0 + tx] = h;
        lo[(size_t)(n0 + i) * Kdim + k0 + tx] =
            __float2bfloat16(v - __bfloat162float(h));
    }
}

__global__ void padzero_k(__nv_bfloat16* __restrict__ a,
                          __nv_bfloat16* __restrict__ b, int n)
{
    int i = blockIdx.x * blockDim.x + threadIdx.x;
    if (i < n) { a[i] = __float2bfloat16(0.0f); b[i] = __float2bfloat16(0.0f); }
}

// ---------------------------------------------------------------------------
// mma.sync split-bf16 GEMM: C[M,N] = A[M,K] @ B_t[N,K]^T (fp32 out)
// CTA tile 128x128, BK=32, 256 threads (8 warps, 4Mx2N), warp tile 32x64.
// 3-stage cp.async pipeline (round-5 config). Term-major MMA issue order.
// ---------------------------------------------------------------------------
constexpr int BK = 32;
constexpr int ROWB = 80;
constexpr int TILEB = 128 * ROWB;
constexpr int STAGEB = 4 * TILEB;
constexpr int NSTAGE = 3;
constexpr int SMEM_MMA = NSTAGE * STAGEB;  // 122880 B

__global__ void __launch_bounds__(256, 1) mma_gemm_k(
    const __nv_bfloat16* __restrict__ Ah, const __nv_bfloat16* __restrict__ Al,
    const __nv_bfloat16* __restrict__ Bh, const __nv_bfloat16* __restrict__ Bl,
    float* __restrict__ C, int Kdim, int ldc)
{
    extern __shared__ __align__(16) char smem[];
    const uint32_t sb = (uint32_t)__cvta_generic_to_shared(smem);
    const int tid = threadIdx.x;
    const int wid = tid >> 5, lid = tid & 31;
    const int warpM = wid & 3, warpN = wid >> 2;   // 4 x 2

    const int rowBase = blockIdx.y * 128;
    const int colBase = blockIdx.x * 128;
    const int nch = Kdim / BK;

    float acc[2][8][4];
#pragma unroll
    for (int i = 0; i < 2; i++)
#pragma unroll
        for (int j = 0; j < 8; j++)
#pragma unroll
            for (int q = 0; q < 4; q++) acc[i][j][q] = 0.0f;

    auto load_chunk = [&](int c, int buf) {
        const uint32_t st = sb + buf * STAGEB;
        const int k0 = c * BK;
#pragma unroll
        for (int ch = tid; ch < 512; ch += 256) {
            const int row = ch >> 2;
            const int kc = ch & 3;
            const uint32_t so = row * ROWB + kc * 16;
            const size_t go = (size_t)k0 + kc * 8;
            cp_async16(st + so,             Ah + (size_t)(rowBase + row) * Kdim + go);
            cp_async16(st + TILEB + so,     Al + (size_t)(rowBase + row) * Kdim + go);
            cp_async16(st + 2 * TILEB + so, Bh + (size_t)(colBase + row) * Kdim + go);
            cp_async16(st + 3 * TILEB + so, Bl + (size_t)(colBase + row) * Kdim + go);
        }
        cp_commit();
    };

#pragma unroll
    for (int i = 0; i < NSTAGE; i++) {
        if (i < nch) load_chunk(i, i);
        else cp_commit();
    }

    const int lr = lid & 15;
    const int lc16 = (lid >> 4) * 16;

    for (int c = 0; c < nch; c++) {
        const int buf = c % NSTAGE;
        cp_wait<NSTAGE - 1>();
        __syncthreads();

        const uint32_t st = sb + buf * STAGEB;
#pragma unroll
        for (int kk = 0; kk < 2; kk++) {
            const uint32_t kb = kk * 32;
            uint32_t ah[2][4], al[2][4];
#pragma unroll
            for (int mf = 0; mf < 2; mf++) {
                const uint32_t a =
                    st + (warpM * 32 + mf * 16 + lr) * ROWB + kb + lc16;
                ldsm_x4(ah[mf], a);
                ldsm_x4(al[mf], a + TILEB);
            }
            uint32_t bh[8][2], bl[8][2];
#pragma unroll
            for (int np = 0; np < 4; np++) {
                const uint32_t a =
                    st + 2 * TILEB + (warpN * 64 + np * 16 + lr) * ROWB + kb + lc16;
                uint32_t t[4];
                ldsm_x4(t, a);
                bh[2 * np][0] = t[0]; bh[2 * np + 1][0] = t[1];
                bh[2 * np][1] = t[2]; bh[2 * np + 1][1] = t[3];
                ldsm_x4(t, a + TILEB);
                bl[2 * np][0] = t[0]; bl[2 * np + 1][0] = t[1];
                bl[2 * np][1] = t[2]; bl[2 * np + 1][1] = t[3];
            }
            // term-major issue order: reuse distance per accumulator = 16 MMAs
#pragma unroll
            for (int mf = 0; mf < 2; mf++)
#pragma unroll
                for (int nf = 0; nf < 8; nf++)
                    mma16816(acc[mf][nf], ah[mf], bh[nf][0], bh[nf][1]);
#pragma unroll
            for (int mf = 0; mf < 2; mf++)
#pragma unroll
                for (int nf = 0; nf < 8; nf++)
                    mma16816(acc[mf][nf], ah[mf], bl[nf][0], bl[nf][1]);
#pragma unroll
            for (int mf = 0; mf < 2; mf++)
#pragma unroll
                for (int nf = 0; nf < 8; nf++)
                    mma16816(acc[mf][nf], al[mf], bh[nf][0], bh[nf][1]);
        }
        __syncthreads();
        if (c + NSTAGE < nch) load_chunk(c + NSTAGE, buf);
        else cp_commit();
    }

    const int r = lid >> 2, cq = (lid & 3) * 2;
    float* Cw = C + (size_t)(rowBase + warpM * 32) * ldc + colBase + warpN * 64;
#pragma unroll
    for (int mf = 0; mf < 2; mf++)
#pragma unroll
        for (int nf = 0; nf < 8; nf++) {
            float2 v0 = make_float2(acc[mf][nf][0], acc[mf][nf][1]);
            float2 v1 = make_float2(acc[mf][nf][2], acc[mf][nf][3]);
            *(float2*)&Cw[(size_t)(mf * 16 + r) * ldc + nf * 8 + cq] = v0;
            *(float2*)&Cw[(size_t)(mf * 16 + r + 8) * ldc + nf * 8 + cq] = v1;
        }
}

// ---------------------------------------------------------------------------
// SIMT GEMM (delta). EPI: 0 none, 1 softplus(x + bias[col])
// ---------------------------------------------------------------------------
template <int BM, int BN, int BKt, int TM, int TN, int EPI>
__global__ void __launch_bounds__((BM / TM) * (BN / TN))
gemm_k(const float* __restrict__ A, int lda,
       const float* __restrict__ B, int ldb,
       float* __restrict__ C, int ldc,
       int Kdim, const float* __restrict__ bias)
{
    constexpr int THREADS = (BM / TM) * (BN / TN);
    __shared__ __align__(16) float As[BKt][BM];
    __shared__ __align__(16) float Bs[BKt][BN];

    const int tid = threadIdx.x;
    const int blockRow = blockIdx.y * BM;
    const int blockCol = blockIdx.x * BN;
    const int tRow = (tid / (BN / TN)) * TM;
    const int tCol = (tid % (BN / TN)) * TN;

    float acc[TM][TN];
#pragma unroll
    for (int i = 0; i < TM; i++)
#pragma unroll
        for (int j = 0; j < TN; j++) acc[i][j] = 0.0f;

    constexpr int A_F4_PER_ROW = BKt / 4;
    const int aRow = tid / A_F4_PER_ROW;
    const int aK = (tid % A_F4_PER_ROW) * 4;
    constexpr int A_ROWS_PER_PASS = THREADS / A_F4_PER_ROW;
    constexpr int B_F4_PER_ROW = BN / 4;
    const int bRow = tid / B_F4_PER_ROW;
    const int bCol = (tid % B_F4_PER_ROW) * 4;
    constexpr int B_ROWS_PER_PASS = THREADS / B_F4_PER_ROW;

    for (int k0 = 0; k0 < Kdim; k0 += BKt) {
#pragma unroll 1
        for (int rr = aRow; rr < BM; rr += A_ROWS_PER_PASS) {
            float4 v = *(const float4*)&A[(size_t)(blockRow + rr) * lda + k0 + aK];
            As[aK + 0][rr] = v.x; As[aK + 1][rr] = v.y;
            As[aK + 2][rr] = v.z; As[aK + 3][rr] = v.w;
        }
#pragma unroll 1
        for (int rr = bRow; rr < BKt; rr += B_ROWS_PER_PASS) {
            *(float4*)&Bs[rr][bCol] =
                *(const float4*)&B[(size_t)(k0 + rr) * ldb + blockCol + bCol];
        }
        __syncthreads();

#pragma unroll
        for (int kk = 0; kk < BKt; kk++) {
            float a[TM], bf[TN];
#pragma unroll
            for (int i = 0; i < TM; i += 4) {
                float4 v = *(const float4*)&As[kk][tRow + i];
                a[i] = v.x; a[i + 1] = v.y; a[i + 2] = v.z; a[i + 3] = v.w;
            }
#pragma unroll
            for (int j = 0; j < TN; j += 4) {
                float4 v = *(const float4*)&Bs[kk][tCol + j];
                bf[j] = v.x; bf[j + 1] = v.y; bf[j + 2] = v.z; bf[j + 3] = v.w;
            }
#pragma unroll
            for (int i = 0; i < TM; i++)
#pragma unroll
                for (int j = 0; j < TN; j++)
                    acc[i][j] = fmaf(a[i], bf[j], acc[i][j]);
        }
        __syncthreads();
    }

#pragma unroll
    for (int i = 0; i < TM; i++) {
        const int rr = blockRow + tRow + i;
#pragma unroll
        for (int j = 0; j < TN; j += 4) {
            const int cc = blockCol + tCol + j;
            float4 v;
            float v0 = acc[i][j + 0], v1 = acc[i][j + 1],
                  v2 = acc[i][j + 2], v3 = acc[i][j + 3];
            if (EPI == 1) {
                v0 = softplusf(v0 + bias[cc + 0]);
                v1 = softplusf(v1 + bias[cc + 1]);
                v2 = softplusf(v2 + bias[cc + 2]);
                v3 = softplusf(v3 + bias[cc + 3]);
            }
            v.x = v0; v.y = v1; v.z = v2; v.w = v3;
            *(float4*)&C[(size_t)rr * ldc + cc] = v;
        }
    }
}

// ---------------------------------------------------------------------------
// Depthwise causal conv (width 4) + SiLU + fused bf16 split output
// ---------------------------------------------------------------------------
__global__ void conv_silu_k(const float* __restrict__ xz,
                            const float* __restrict__ w,
                            const float* __restrict__ bias,
                            float* __restrict__ xc,
                            __nv_bfloat16* __restrict__ xch,
                            __nv_bfloat16* __restrict__ xcl)
{
    const int idx = blockIdx.x * blockDim.x + threadIdx.x;
    if (idx >= M * DI) return;
    const int d = idx % DI;
    const int m = idx / DI;
    const int l = m % Lsz;

    float acc = bias[d];
    const float w0 = w[d * 4 + 0], w1 = w[d * 4 + 1],
                w2 = w[d * 4 + 2], w3 = w[d * 4 + 3];
    if (l >= 3) acc = fmaf(w0, xz[(size_t)(m - 3) * XZ_N + d], acc);
    if (l >= 2) acc = fmaf(w1, xz[(size_t)(m - 2) * XZ_N + d], acc);
    if (l >= 1) acc = fmaf(w2, xz[(size_t)(m - 1) * XZ_N + d], acc);
    acc = fmaf(w3, xz[(size_t)m * XZ_N + d], acc);
    const float v = acc * sigmoidf_fast(acc);
    xc[idx] = v;
    const __nv_bfloat16 h = __float2bfloat16(v);
    xch[idx] = h;
    xcl[idx] = __float2bfloat16(v - __bfloat162float(h));
}

// ---------------------------------------------------------------------------
// Parallel selective scan (3 phases).
// ---------------------------------------------------------------------------
__global__ void __launch_bounds__(256) scan1_k(
    const float* __restrict__ delta_, const float* __restrict__ xc,
    const float* __restrict__ dbcp, const float* __restrict__ A_log,
    float* __restrict__ yz, float* __restrict__ hend, float* __restrict__ ptot)
{
    const int tid = threadIdx.x;
    const int s = tid & 15;
    const int g = blockIdx.x * 16 + (tid >> 4);
    const int ch = g & (NCH - 1);
    const int c = g >> 12;
    const int b = ch >> 11, d = ch & (DI - 1);

    const float Aneg = -__expf(A_log[d * DS + s]);
    float h = 0.0f, p = 1.0f;
    const size_t mbase = (size_t)b * Lsz + c * LC;

    for (int k = 0; k < LC; k++) {
        const size_t m = mbase + k;
        const float delta = delta_[m * DI + d];
        const float u = xc[m * DI + d];
        const float Bv = dbcp[m * DBC_LD + DR + s];
        const float Cv = dbcp[m * DBC_LD + DR + DS + s];
        const float a = __expf(delta * Aneg);
        p *= a;
        h = fmaf(a, h, delta * u * Bv);
        float yp = h * Cv;
        yp += __shfl_xor_sync(0xffffffffu, yp, 1);
        yp += __shfl_xor_sync(0xffffffffu, yp, 2);
        yp += __shfl_xor_sync(0xffffffffu, yp, 4);
        yp += __shfl_xor_sync(0xffffffffu, yp, 8);
        if (s == 0) yz[m * DI + d] = yp;
    }
    const size_t idx = (size_t)c * (NCH * DS) + ch * DS + s;
    hend[idx] = h;
    ptot[idx] = p;
}

__global__ void __launch_bounds__(256) combine_k(
    const float* __restrict__ hend, const float* __restrict__ ptot,
    float* __restrict__ hin)
{
    const int i = blockIdx.x * 256 + threadIdx.x;  // NCH*DS = 65536
    float H = 0.0f;
#pragma unroll
    for (int c = 0; c < NC; c++) {
        const size_t idx = (size_t)c * (NCH * DS) + i;
        hin[idx] = H;
        H = fmaf(ptot[idx], H, hend[idx]);
    }
}

__global__ void __launch_bounds__(256) scan2_k(
    const float* __restrict__ delta_, const float* __restrict__ xc,
    const float* __restrict__ dbcp, const float* __restrict__ xz,
    const float* __restrict__ A_log, const float* __restrict__ D_skip,
    const float* __restrict__ hin_, const float* __restrict__ yz,
    __nv_bfloat16* __restrict__ yzh, __nv_bfloat16* __restrict__ yzl)
{
    const int tid = threadIdx.x;
    const int s = tid & 15;
    const int g = blockIdx.x * 16 + (tid >> 4);
    const int ch = g & (NCH - 1);
    const int c = g >> 12;
    const int b = ch >> 11, d = ch & (DI - 1);

    const float Aneg = -__expf(A_log[d * DS + s]);
    const float dskip = D_skip[d];
    const float hin = hin_[(size_t)c * (NCH * DS) + ch * DS + s];
    float p = 1.0f;
    const size_t mbase = (size_t)b * Lsz + c * LC;

    for (int k = 0; k < LC; k++) {
        const size_t m = mbase + k;
        const float delta = delta_[m * DI + d];
        const float Cv = dbcp[m * DBC_LD + DR + DS + s];
        const float a = __expf(delta * Aneg);
        p *= a;
        float yc = hin * p * Cv;
        yc += __shfl_xor_sync(0xffffffffu, yc, 1);
        yc += __shfl_xor_sync(0xffffffffu, yc, 2);
        yc += __shfl_xor_sync(0xffffffffu, yc, 4);
        yc += __shfl_xor_sync(0xffffffffu, yc, 8);
        if (s == 0) {
            const float u = xc[m * DI + d];
            const float z = xz[m * XZ_N + DI + d];
            const float y = yz[m * DI + d] + yc + u * dskip;
            const float val = y * (z * sigmoidf_fast(z));
            const __nv_bfloat16 hh = __float2bfloat16(val);
            yzh[m * DI + d] = hh;
            yzl[m * DI + d] = __float2bfloat16(val - __bfloat162float(hh));
        }
    }
}

// ---------------------------------------------------------------------------
extern "C" void kernel_launch(void* const* d_in, const int* in_sizes, int n_in,
                              void* d_out, int out_size)
{
    const float* x      = (const float*)d_in[0];
    const float* W_in   = (const float*)d_in[1];
    const float* conv_w = (const float*)d_in[2];
    const float* conv_b = (const float*)d_in[3];
    const float* W_xprj = (const float*)d_in[4];
    const float* W_dt   = (const float*)d_in[5];
    const float* b_dt   = (const float*)d_in[6];
    const float* A_log  = (const float*)d_in[7];
    const float* D_skip = (const float*)d_in[8];
    const float* W_out  = (const float*)d_in[9];
    float* out = (float*)d_out;

    float *xz, *xc, *dbcp, *delta, *yz, *hend, *ptot, *hin;
    cudaGetSymbolAddress((void**)&xz, g_xz);
    cudaGetSymbolAddress((void**)&xc, g_xc);
    cudaGetSymbolAddress((void**)&dbcp, g_dbcp);
    cudaGetSymbolAddress((void**)&delta, g_delta);
    cudaGetSymbolAddress((void**)&yz, g_yz);
    cudaGetSymbolAddress((void**)&hend, g_hend);
    cudaGetSymbolAddress((void**)&ptot, g_ptot);
    cudaGetSymbolAddress((void**)&hin, g_hin);
    __nv_bfloat16 *xh, *xl, *winh, *winl, *xch, *xcl, *wxh, *wxl,
                  *yzh, *yzl, *wouth, *woutl;
    cudaGetSymbolAddress((void**)&xh, g_xh);
    cudaGetSymbolAddress((void**)&xl, g_xl);
    cudaGetSymbolAddress((void**)&winh, g_winh);
    cudaGetSymbolAddress((void**)&winl, g_winl);
    cudaGetSymbolAddress((void**)&xch, g_xch);
    cudaGetSymbolAddress((void**)&xcl, g_xcl);
    cudaGetSymbolAddress((void**)&wxh, g_wxh);
    cudaGetSymbolAddress((void**)&wxl, g_wxl);
    cudaGetSymbolAddress((void**)&yzh, g_yzh);
    cudaGetSymbolAddress((void**)&yzl, g_yzl);
    cudaGetSymbolAddress((void**)&wouth, g_wouth);
    cudaGetSymbolAddress((void**)&woutl, g_woutl);

    cudaFuncSetAttribute(mma_gemm_k, cudaFuncAttributeMaxDynamicSharedMemorySize,
                         SMEM_MMA);

    // 0) operand prep
    split_k<<<(M * DM / 4 + 255) / 256, 256>>>(x, xh, xl, M * DM / 4);
    {   // W_in [DM, XZ_N] -> [XZ_N, DM]
        dim3 grid(XZ_N / 32, DM / 32);
        tsplit_k<<<grid, dim3(32, 8)>>>(W_in, DM, XZ_N, winh, winl);
    }
    {   // W_out [DI, DM] -> [DM, DI]
        dim3 grid(DM / 32, DI / 32);
        tsplit_k<<<grid, dim3(32, 8)>>>(W_out, DI, DM, wouth, woutl);
    }
    {   // W_xproj [DI, 96] -> [96, DI], pad rows 96..127 with zeros
        dim3 grid(96 / 32, DI / 32);
        tsplit_k<<<grid, dim3(32, 8)>>>(W_xprj, DI, 96, wxh, wxl);
        padzero_k<<<(32 * DI + 255) / 256, 256>>>(wxh + (size_t)96 * DI,
                                                  wxl + (size_t)96 * DI, 32 * DI);
    }

    // 1) xz = x @ W_in
    {
        dim3 grid(XZ_N / 128, M / 128);
        mma_gemm_k<<<grid, 256, SMEM_MMA>>>(xh, xl, winh, winl, xz, DM, XZ_N);
    }
    // 2) conv + silu (+ bf16 split)
    conv_silu_k<<<(M * DI) / 256, 256>>>(xz, conv_w, conv_b, xc, xch, xcl);
    // 3) dbc = xc @ W_xproj (mma, padded N=128)
    {
        dim3 grid(1, M / 128);
        mma_gemm_k<<<grid, 256, SMEM_MMA>>>(xch, xcl, wxh, wxl, dbcp, DI, DBC_LD);
    }
    // 4) delta = softplus(dt_lo @ W_dt + b_dt) (SIMT, K=64)
    {
        dim3 grid(DI / 128, M / 128);
        gemm_k<128, 128, 8, 8, 8, 1><<<grid, 256>>>(dbcp, DBC_LD, W_dt, DI,
                                                    delta, DI, DR, b_dt);
    }
    // 5) parallel selective scan
    scan1_k<<<(NCH * NC) / 16, 256>>>(delta, xc, dbcp, A_log, yz, hend, ptot);
    combine_k<<<(NCH * DS) / 256, 256>>>(hend, ptot, hin);
    scan2_k<<<(NCH * NC) / 16, 256>>>(delta, xc, dbcp, xz, A_log, D_skip, hin,
                                      yz, yzh, yzl);
    // 6) out = yz @ W_out
    {
        dim3 grid(DM / 128, M / 128);
        mma_gemm_k<<<grid, 256, SMEM_MMA>>>(yzh, yzl, wouth, woutl, out, DI, DM);
    }
}

// round 9
// speedup vs baseline: 1.5322x; 1.5322x over previous
#include <cuda_runtime.h>
#include <cuda_bf16.h>
#include <math.h>
#include <stdint.h>

// Problem constants
constexpr int Bsz = 2, Lsz = 2048, DM = 1024, DI = 2048, DS = 16, DR = 64;
constexpr int M = Bsz * Lsz;          // 4096
constexpr int XZ_N = 2 * DI;          // 4096
constexpr int DBC_LD = 128;           // padded dbc row stride (real cols: 96)
constexpr int NC = 32, LC = 64;       // scan chunking: 32 chunks x 64 steps
constexpr int NCH = Bsz * DI;         // 4096 channels
constexpr int KSPLIT = 4;             // split-K factor for dbc GEMM

// fp32 scratch
__device__ float g_xz[(size_t)M * XZ_N];
__device__ float g_xc[(size_t)M * DI];
__device__ float g_dbcp[(size_t)M * DBC_LD];
__device__ float g_dbcpart[(size_t)KSPLIT * M * DBC_LD];
__device__ float g_delta[(size_t)M * DI];
__device__ float g_yz[(size_t)M * DI];           // raw local scan y
// scan chunk state
__device__ float g_hend[(size_t)NC * NCH * DS];
__device__ float g_ptot[(size_t)NC * NCH * DS];
__device__ float g_hin [(size_t)NC * NCH * DS];
// bf16 split operands (A row-major [rows,K]; B stored K-major as [N,K])
__device__ __nv_bfloat16 g_xh[(size_t)M * DM],      g_xl[(size_t)M * DM];
__device__ __nv_bfloat16 g_winh[(size_t)XZ_N * DM], g_winl[(size_t)XZ_N * DM];
__device__ __nv_bfloat16 g_xch[(size_t)M * DI],     g_xcl[(size_t)M * DI];
__device__ __nv_bfloat16 g_wxh[(size_t)DBC_LD * DI], g_wxl[(size_t)DBC_LD * DI];
__device__ __nv_bfloat16 g_yzh[(size_t)M * DI],     g_yzl[(size_t)M * DI];
__device__ __nv_bfloat16 g_wouth[(size_t)DM * DI],  g_woutl[(size_t)DM * DI];

__device__ __forceinline__ float sigmoidf_fast(float x) {
    return 1.0f / (1.0f + __expf(-x));
}
__device__ __forceinline__ float softplusf(float x) {
    return (x > 20.0f) ? x : log1pf(expf(x));
}

// ---------------------------------------------------------------------------
// PTX helpers (portable sm_80+ PTX only)
// ---------------------------------------------------------------------------
__device__ __forceinline__ void cp_async16(uint32_t dst, const void* src) {
    asm volatile("cp.async.cg.shared.global [%0], [%1], 16;"
                 :: "r"(dst), "l"(src) : "memory");
}
__device__ __forceinline__ void cp_commit() {
    asm volatile("cp.async.commit_group;" ::: "memory");
}
template <int N>
__device__ __forceinline__ void cp_wait() {
    asm volatile("cp.async.wait_group %0;" :: "n"(N) : "memory");
}
__device__ __forceinline__ void ldsm_x4(uint32_t* r, uint32_t addr) {
    asm volatile("ldmatrix.sync.aligned.m8n8.x4.shared.b16 {%0,%1,%2,%3}, [%4];"
                 : "=r"(r[0]), "=r"(r[1]), "=r"(r[2]), "=r"(r[3]) : "r"(addr));
}
__device__ __forceinline__ void mma16816(float* c, const uint32_t* a,
                                         uint32_t b0, uint32_t b1) {
    asm volatile(
        "mma.sync.aligned.m16n8k16.row.col.f32.bf16.bf16.f32 "
        "{%0,%1,%2,%3}, {%4,%5,%6,%7}, {%8,%9}, {%0,%1,%2,%3};"
        : "+f"(c[0]), "+f"(c[1]), "+f"(c[2]), "+f"(c[3])
        : "r"(a[0]), "r"(a[1]), "r"(a[2]), "r"(a[3]), "r"(b0), "r"(b1));
}

// ---------------------------------------------------------------------------
// Split fp32 -> (hi, lo) bf16, same layout
// ---------------------------------------------------------------------------
__global__ void split_k(const float* __restrict__ in,
                        __nv_bfloat16* __restrict__ hi,
                        __nv_bfloat16* __restrict__ lo, int n4)
{
    int i = blockIdx.x * blockDim.x + threadIdx.x;
    if (i >= n4) return;
    float4 v = ((const float4*)in)[i];
    __nv_bfloat16 h0 = __float2bfloat16(v.x);
    __nv_bfloat16 h1 = __float2bfloat16(v.y);
    __nv_bfloat16 h2 = __float2bfloat16(v.z);
    __nv_bfloat16 h3 = __float2bfloat16(v.w);
    ushort4 hh, ll;
    hh.x = __bfloat16_as_ushort(h0); hh.y = __bfloat16_as_ushort(h1);
    hh.z = __bfloat16_as_ushort(h2); hh.w = __bfloat16_as_ushort(h3);
    ll.x = __bfloat16_as_ushort(__float2bfloat16(v.x - __bfloat162float(h0)));
    ll.y = __bfloat16_as_ushort(__float2bfloat16(v.y - __bfloat162float(h1)));
    ll.z = __bfloat16_as_ushort(__float2bfloat16(v.z - __bfloat162float(h2)));
    ll.w = __bfloat16_as_ushort(__float2bfloat16(v.w - __bfloat162float(h3)));
    ((ushort4*)hi)[i] = hh;
    ((ushort4*)lo)[i] = ll;
}

// ---------------------------------------------------------------------------
// Transpose + split: in [K,N] fp32 row-major -> hi/lo [N,K] bf16
// ---------------------------------------------------------------------------
__global__ void tsplit_k(const float* __restrict__ in, int Kdim, int Ndim,
                         __nv_bfloat16* __restrict__ hi,
                         __nv_bfloat16* __restrict__ lo)
{
    __shared__ float t[32][33];
    const int n0 = blockIdx.x * 32, k0 = blockIdx.y * 32;
    const int tx = threadIdx.x, ty = threadIdx.y;  // block (32, 8)
    for (int i = ty; i < 32; i += 8)
        t[i][tx] = in[(size_t)(k0 + i) * Ndim + n0 + tx];
    __syncthreads();
    for (int i = ty; i < 32; i += 8) {
        float v = t[tx][i];  // = in[k0+tx][n0+i]
        __nv_bfloat16 h = __float2bfloat16(v);
        hi[(size_t)(n0 + i) * Kdim + k0 + tx] = h;
        lo[(size_t)(n0 + i) * Kdim + k0 + tx] =
            __float2bfloat16(v - __bfloat162float(h));
    }
}

__global__ void padzero_k(__nv_bfloat16* __restrict__ a,
                          __nv_bfloat16* __restrict__ b, int n)
{
    int i = blockIdx.x * blockDim.x + threadIdx.x;
    if (i < n) { a[i] = __float2bfloat16(0.0f); b[i] = __float2bfloat16(0.0f); }
}

// Reduce KSPLIT partial C buffers into one (float4 vectorized)
__global__ void reduce_part_k(const float* __restrict__ part,
                              float* __restrict__ out, int n4, size_t zstride4)
{
    int i = blockIdx.x * blockDim.x + threadIdx.x;
    if (i >= n4) return;
    float4 a = ((const float4*)part)[i];
#pragma unroll
    for (int z = 1; z < KSPLIT; z++) {
        float4 b = ((const float4*)part)[(size_t)z * zstride4 + i];
        a.x += b.x; a.y += b.y; a.z += b.z; a.w += b.w;
    }
    ((float4*)out)[i] = a;
}

// ---------------------------------------------------------------------------
// mma.sync split-bf16 GEMM: C[M,N] = A[M,K] @ B_t[N,K]^T (fp32 out)
// CTA tile 128x128, BK=32, 256 threads (8 warps, 4Mx2N), warp tile 32x64.
// 3-stage cp.async pipeline, interleaved MMA order (round-5 proven config).
// Split-K: blockIdx.z selects K-slice [z*kspan, (z+1)*kspan); output goes to
// C + z*zstride (zstride=0, gridDim.z=1 for unsplit calls).
// ---------------------------------------------------------------------------
constexpr int BK = 32;
constexpr int ROWB = 80;
constexpr int TILEB = 128 * ROWB;
constexpr int STAGEB = 4 * TILEB;
constexpr int NSTAGE = 3;
constexpr int SMEM_MMA = NSTAGE * STAGEB;  // 122880 B

__global__ void __launch_bounds__(256, 1) mma_gemm_k(
    const __nv_bfloat16* __restrict__ Ah, const __nv_bfloat16* __restrict__ Al,
    const __nv_bfloat16* __restrict__ Bh, const __nv_bfloat16* __restrict__ Bl,
    float* __restrict__ C, int lda, int ldc, int kspan, size_t zstride)
{
    extern __shared__ __align__(16) char smem[];
    const uint32_t sb = (uint32_t)__cvta_generic_to_shared(smem);
    const int tid = threadIdx.x;
    const int wid = tid >> 5, lid = tid & 31;
    const int warpM = wid & 3, warpN = wid >> 2;   // 4 x 2

    const int rowBase = blockIdx.y * 128;
    const int colBase = blockIdx.x * 128;
    const int kstart = blockIdx.z * kspan;
    const int nch = kspan / BK;
    C += (size_t)blockIdx.z * zstride;

    float acc[2][8][4];
#pragma unroll
    for (int i = 0; i < 2; i++)
#pragma unroll
        for (int j = 0; j < 8; j++)
#pragma unroll
            for (int q = 0; q < 4; q++) acc[i][j][q] = 0.0f;

    auto load_chunk = [&](int c, int buf) {
        const uint32_t st = sb + buf * STAGEB;
        const int k0 = kstart + c * BK;
#pragma unroll
        for (int ch = tid; ch < 512; ch += 256) {
            const int row = ch >> 2;
            const int kc = ch & 3;
            const uint32_t so = row * ROWB + kc * 16;
            const size_t go = (size_t)k0 + kc * 8;
            cp_async16(st + so,             Ah + (size_t)(rowBase + row) * lda + go);
            cp_async16(st + TILEB + so,     Al + (size_t)(rowBase + row) * lda + go);
            cp_async16(st + 2 * TILEB + so, Bh + (size_t)(colBase + row) * lda + go);
            cp_async16(st + 3 * TILEB + so, Bl + (size_t)(colBase + row) * lda + go);
        }
        cp_commit();
    };

    load_chunk(0, 0);
    load_chunk(1, 1);
    load_chunk(2, 2);

    const int lr = lid & 15;
    const int lc16 = (lid >> 4) * 16;

    for (int c = 0; c < nch; c++) {
        const int buf = c % NSTAGE;
        cp_wait<NSTAGE - 1>();
        __syncthreads();

        const uint32_t st = sb + buf * STAGEB;
#pragma unroll
        for (int kk = 0; kk < 2; kk++) {
            const uint32_t kb = kk * 32;
            uint32_t ah[2][4], al[2][4];
#pragma unroll
            for (int mf = 0; mf < 2; mf++) {
                const uint32_t a =
                    st + (warpM * 32 + mf * 16 + lr) * ROWB + kb + lc16;
                ldsm_x4(ah[mf], a);
                ldsm_x4(al[mf], a + TILEB);
            }
            uint32_t bh[8][2], bl[8][2];
#pragma unroll
            for (int np = 0; np < 4; np++) {
                const uint32_t a =
                    st + 2 * TILEB + (warpN * 64 + np * 16 + lr) * ROWB + kb + lc16;
                uint32_t t[4];
                ldsm_x4(t, a);
                bh[2 * np][0] = t[0]; bh[2 * np + 1][0] = t[1];
                bh[2 * np][1] = t[2]; bh[2 * np + 1][1] = t[3];
                ldsm_x4(t, a + TILEB);
                bl[2 * np][0] = t[0]; bl[2 * np + 1][0] = t[1];
                bl[2 * np][1] = t[2]; bl[2 * np + 1][1] = t[3];
            }
            // interleaved MMA order (proven fastest)
#pragma unroll
            for (int mf = 0; mf < 2; mf++)
#pragma unroll
                for (int nf = 0; nf < 8; nf++) {
                    mma16816(acc[mf][nf], ah[mf], bh[nf][0], bh[nf][1]);
                    mma16816(acc[mf][nf], ah[mf], bl[nf][0], bl[nf][1]);
                    mma16816(acc[mf][nf], al[mf], bh[nf][0], bh[nf][1]);
                }
        }
        __syncthreads();
        if (c + NSTAGE < nch) load_chunk(c + NSTAGE, buf);
        else cp_commit();
    }

    const int r = lid >> 2, cq = (lid & 3) * 2;
    float* Cw = C + (size_t)(rowBase + warpM * 32) * ldc + colBase + warpN * 64;
#pragma unroll
    for (int mf = 0; mf < 2; mf++)
#pragma unroll
        for (int nf = 0; nf < 8; nf++) {
            float2 v0 = make_float2(acc[mf][nf][0], acc[mf][nf][1]);
            float2 v1 = make_float2(acc[mf][nf][2], acc[mf][nf][3]);
            *(float2*)&Cw[(size_t)(mf * 16 + r) * ldc + nf * 8 + cq] = v0;
            *(float2*)&Cw[(size_t)(mf * 16 + r + 8) * ldc + nf * 8 + cq] = v1;
        }
}

// ---------------------------------------------------------------------------
// SIMT GEMM (delta). EPI: 0 none, 1 softplus(x + bias[col])
// ---------------------------------------------------------------------------
template <int BM, int BN, int BKt, int TM, int TN, int EPI>
__global__ void __launch_bounds__((BM / TM) * (BN / TN))
gemm_k(const float* __restrict__ A, int lda,
       const float* __restrict__ B, int ldb,
       float* __restrict__ C, int ldc,
       int Kdim, const float* __restrict__ bias)
{
    constexpr int THREADS = (BM / TM) * (BN / TN);
    __shared__ __align__(16) float As[BKt][BM];
    __shared__ __align__(16) float Bs[BKt][BN];

    const int tid = threadIdx.x;
    const int blockRow = blockIdx.y * BM;
    const int blockCol = blockIdx.x * BN;
    const int tRow = (tid / (BN / TN)) * TM;
    const int tCol = (tid % (BN / TN)) * TN;

    float acc[TM][TN];
#pragma unroll
    for (int i = 0; i < TM; i++)
#pragma unroll
        for (int j = 0; j < TN; j++) acc[i][j] = 0.0f;

    constexpr int A_F4_PER_ROW = BKt / 4;
    const int aRow = tid / A_F4_PER_ROW;
    const int aK = (tid % A_F4_PER_ROW) * 4;
    constexpr int A_ROWS_PER_PASS = THREADS / A_F4_PER_ROW;
    constexpr int B_F4_PER_ROW = BN / 4;
    const int bRow = tid / B_F4_PER_ROW;
    const int bCol = (tid % B_F4_PER_ROW) * 4;
    constexpr int B_ROWS_PER_PASS = THREADS / B_F4_PER_ROW;

    for (int k0 = 0; k0 < Kdim; k0 += BKt) {
#pragma unroll 1
        for (int rr = aRow; rr < BM; rr += A_ROWS_PER_PASS) {
            float4 v = *(const float4*)&A[(size_t)(blockRow + rr) * lda + k0 + aK];
            As[aK + 0][rr] = v.x; As[aK + 1][rr] = v.y;
            As[aK + 2][rr] = v.z; As[aK + 3][rr] = v.w;
        }
#pragma unroll 1
        for (int rr = bRow; rr < BKt; rr += B_ROWS_PER_PASS) {
            *(float4*)&Bs[rr][bCol] =
                *(const float4*)&B[(size_t)(k0 + rr) * ldb + blockCol + bCol];
        }
        __syncthreads();

#pragma unroll
        for (int kk = 0; kk < BKt; kk++) {
            float a[TM], bf[TN];
#pragma unroll
            for (int i = 0; i < TM; i += 4) {
                float4 v = *(const float4*)&As[kk][tRow + i];
                a[i] = v.x; a[i + 1] = v.y; a[i + 2] = v.z; a[i + 3] = v.w;
            }
#pragma unroll
            for (int j = 0; j < TN; j += 4) {
                float4 v = *(const float4*)&Bs[kk][tCol + j];
                bf[j] = v.x; bf[j + 1] = v.y; bf[j + 2] = v.z; bf[j + 3] = v.w;
            }
#pragma unroll
            for (int i = 0; i < TM; i++)
#pragma unroll
                for (int j = 0; j < TN; j++)
                    acc[i][j] = fmaf(a[i], bf[j], acc[i][j]);
        }
        __syncthreads();
    }

#pragma unroll
    for (int i = 0; i < TM; i++) {
        const int rr = blockRow + tRow + i;
#pragma unroll
        for (int j = 0; j < TN; j += 4) {
            const int cc = blockCol + tCol + j;
            float4 v;
            float v0 = acc[i][j + 0], v1 = acc[i][j + 1],
                  v2 = acc[i][j + 2], v3 = acc[i][j + 3];
            if (EPI == 1) {
                v0 = softplusf(v0 + bias[cc + 0]);
                v1 = softplusf(v1 + bias[cc + 1]);
                v2 = softplusf(v2 + bias[cc + 2]);
                v3 = softplusf(v3 + bias[cc + 3]);
            }
            v.x = v0; v.y = v1; v.z = v2; v.w = v3;
            *(float4*)&C[(size_t)rr * ldc + cc] = v;
        }
    }
}

// ---------------------------------------------------------------------------
// Depthwise causal conv (width 4) + SiLU + fused bf16 split output
// ---------------------------------------------------------------------------
__global__ void conv_silu_k(const float* __restrict__ xz,
                            const float* __restrict__ w,
                            const float* __restrict__ bias,
                            float* __restrict__ xc,
                            __nv_bfloat16* __restrict__ xch,
                            __nv_bfloat16* __restrict__ xcl)
{
    const int idx = blockIdx.x * blockDim.x + threadIdx.x;
    if (idx >= M * DI) return;
    const int d = idx % DI;
    const int m = idx / DI;
    const int l = m % Lsz;

    float acc = bias[d];
    const float w0 = w[d * 4 + 0], w1 = w[d * 4 + 1],
                w2 = w[d * 4 + 2], w3 = w[d * 4 + 3];
    if (l >= 3) acc = fmaf(w0, xz[(size_t)(m - 3) * XZ_N + d], acc);
    if (l >= 2) acc = fmaf(w1, xz[(size_t)(m - 2) * XZ_N + d], acc);
    if (l >= 1) acc = fmaf(w2, xz[(size_t)(m - 1) * XZ_N + d], acc);
    acc = fmaf(w3, xz[(size_t)m * XZ_N + d], acc);
    const float v = acc * sigmoidf_fast(acc);
    xc[idx] = v;
    const __nv_bfloat16 h = __float2bfloat16(v);
    xch[idx] = h;
    xcl[idx] = __float2bfloat16(v - __bfloat162float(h));
}

// ---------------------------------------------------------------------------
// Parallel selective scan (3 phases).
// ---------------------------------------------------------------------------
__global__ void __launch_bounds__(256) scan1_k(
    const float* __restrict__ delta_, const float* __restrict__ xc,
    const float* __restrict__ dbcp, const float* __restrict__ A_log,
    float* __restrict__ yz, float* __restrict__ hend, float* __restrict__ ptot)
{
    const int tid = threadIdx.x;
    const int s = tid & 15;
    const int g = blockIdx.x * 16 + (tid >> 4);
    const int ch = g & (NCH - 1);
    const int c = g >> 12;
    const int b = ch >> 11, d = ch & (DI - 1);

    const float Aneg = -__expf(A_log[d * DS + s]);
    float h = 0.0f, p = 1.0f;
    const size_t mbase = (size_t)b * Lsz + c * LC;

    for (int k = 0; k < LC; k++) {
        const size_t m = mbase + k;
        const float delta = delta_[m * DI + d];
        const float u = xc[m * DI + d];
        const float Bv = dbcp[m * DBC_LD + DR + s];
        const float Cv = dbcp[m * DBC_LD + DR + DS + s];
        const float a = __expf(delta * Aneg);
        p *= a;
        h = fmaf(a, h, delta * u * Bv);
        float yp = h * Cv;
        yp += __shfl_xor_sync(0xffffffffu, yp, 1);
        yp += __shfl_xor_sync(0xffffffffu, yp, 2);
        yp += __shfl_xor_sync(0xffffffffu, yp, 4);
        yp += __shfl_xor_sync(0xffffffffu, yp, 8);
        if (s == 0) yz[m * DI + d] = yp;
    }
    const size_t idx = (size_t)c * (NCH * DS) + ch * DS + s;
    hend[idx] = h;
    ptot[idx] = p;
}

__global__ void __launch_bounds__(256) combine_k(
    const float* __restrict__ hend, const float* __restrict__ ptot,
    float* __restrict__ hin)
{
    const int i = blockIdx.x * 256 + threadIdx.x;  // NCH*DS = 65536
    float H = 0.0f;
#pragma unroll
    for (int c = 0; c < NC; c++) {
        const size_t idx = (size_t)c * (NCH * DS) + i;
        hin[idx] = H;
        H = fmaf(ptot[idx], H, hend[idx]);
    }
}

__global__ void __launch_bounds__(256) scan2_k(
    const float* __restrict__ delta_, const float* __restrict__ xc,
    const float* __restrict__ dbcp, const float* __restrict__ xz,
    const float* __restrict__ A_log, const float* __restrict__ D_skip,
    const float* __restrict__ hin_, const float* __restrict__ yz,
    __nv_bfloat16* __restrict__ yzh, __nv_bfloat16* __restrict__ yzl)
{
    const int tid = threadIdx.x;
    const int s = tid & 15;
    const int g = blockIdx.x * 16 + (tid >> 4);
    const int ch = g & (NCH - 1);
    const int c = g >> 12;
    const int b = ch >> 11, d = ch & (DI - 1);

    const float Aneg = -__expf(A_log[d * DS + s]);
    const float dskip = D_skip[d];
    const float hin = hin_[(size_t)c * (NCH * DS) + ch * DS + s];
    float p = 1.0f;
    const size_t mbase = (size_t)b * Lsz + c * LC;

    for (int k = 0; k < LC; k++) {
        const size_t m = mbase + k;
        const float delta = delta_[m * DI + d];
        const float Cv = dbcp[m * DBC_LD + DR + DS + s];
        const float a = __expf(delta * Aneg);
        p *= a;
        float yc = hin * p * Cv;
        yc += __shfl_xor_sync(0xffffffffu, yc, 1);
        yc += __shfl_xor_sync(0xffffffffu, yc, 2);
        yc += __shfl_xor_sync(0xffffffffu, yc, 4);
        yc += __shfl_xor_sync(0xffffffffu, yc, 8);
        if (s == 0) {
            const float u = xc[m * DI + d];
            const float z = xz[m * XZ_N + DI + d];
            const float y = yz[m * DI + d] + yc + u * dskip;
            const float val = y * (z * sigmoidf_fast(z));
            const __nv_bfloat16 hh = __float2bfloat16(val);
            yzh[m * DI + d] = hh;
            yzl[m * DI + d] = __float2bfloat16(val - __bfloat162float(hh));
        }
    }
}

// ---------------------------------------------------------------------------
extern "C" void kernel_launch(void* const* d_in, const int* in_sizes, int n_in,
                              void* d_out, int out_size)
{
    const float* x      = (const float*)d_in[0];
    const float* W_in   = (const float*)d_in[1];
    const float* conv_w = (const float*)d_in[2];
    const float* conv_b = (const float*)d_in[3];
    const float* W_xprj = (const float*)d_in[4];
    const float* W_dt   = (const float*)d_in[5];
    const float* b_dt   = (const float*)d_in[6];
    const float* A_log  = (const float*)d_in[7];
    const float* D_skip = (const float*)d_in[8];
    const float* W_out  = (const float*)d_in[9];
    float* out = (float*)d_out;

    float *xz, *xc, *dbcp, *dbcpart, *delta, *yz, *hend, *ptot, *hin;
    cudaGetSymbolAddress((void**)&xz, g_xz);
    cudaGetSymbolAddress((void**)&xc, g_xc);
    cudaGetSymbolAddress((void**)&dbcp, g_dbcp);
    cudaGetSymbolAddress((void**)&dbcpart, g_dbcpart);
    cudaGetSymbolAddress((void**)&delta, g_delta);
    cudaGetSymbolAddress((void**)&yz, g_yz);
    cudaGetSymbolAddress((void**)&hend, g_hend);
    cudaGetSymbolAddress((void**)&ptot, g_ptot);
    cudaGetSymbolAddress((void**)&hin, g_hin);
    __nv_bfloat16 *xh, *xl, *winh, *winl, *xch, *xcl, *wxh, *wxl,
                  *yzh, *yzl, *wouth, *woutl;
    cudaGetSymbolAddress((void**)&xh, g_xh);
    cudaGetSymbolAddress((void**)&xl, g_xl);
    cudaGetSymbolAddress((void**)&winh, g_winh);
    cudaGetSymbolAddress((void**)&winl, g_winl);
    cudaGetSymbolAddress((void**)&xch, g_xch);
    cudaGetSymbolAddress((void**)&xcl, g_xcl);
    cudaGetSymbolAddress((void**)&wxh, g_wxh);
    cudaGetSymbolAddress((void**)&wxl, g_wxl);
    cudaGetSymbolAddress((void**)&yzh, g_yzh);
    cudaGetSymbolAddress((void**)&yzl, g_yzl);
    cudaGetSymbolAddress((void**)&wouth, g_wouth);
    cudaGetSymbolAddress((void**)&woutl, g_woutl);

    cudaFuncSetAttribute(mma_gemm_k, cudaFuncAttributeMaxDynamicSharedMemorySize,
                         SMEM_MMA);

    // 0) operand prep
    split_k<<<(M * DM / 4 + 255) / 256, 256>>>(x, xh, xl, M * DM / 4);
    {   // W_in [DM, XZ_N] -> [XZ_N, DM]
        dim3 grid(XZ_N / 32, DM / 32);
        tsplit_k<<<grid, dim3(32, 8)>>>(W_in, DM, XZ_N, winh, winl);
    }
    {   // W_out [DI, DM] -> [DM, DI]
        dim3 grid(DM / 32, DI / 32);
        tsplit_k<<<grid, dim3(32, 8)>>>(W_out, DI, DM, wouth, woutl);
    }
    {   // W_xproj [DI, 96] -> [96, DI], pad rows 96..127 with zeros
        dim3 grid(96 / 32, DI / 32);
        tsplit_k<<<grid, dim3(32, 8)>>>(W_xprj, DI, 96, wxh, wxl);
        padzero_k<<<(32 * DI + 255) / 256, 256>>>(wxh + (size_t)96 * DI,
                                                  wxl + (size_t)96 * DI, 32 * DI);
    }

    // 1) xz = x @ W_in
    {
        dim3 grid(XZ_N / 128, M / 128, 1);
        mma_gemm_k<<<grid, 256, SMEM_MMA>>>(xh, xl, winh, winl, xz, DM, XZ_N,
                                            DM, 0);
    }
    // 2) conv + silu (+ bf16 split)
    conv_silu_k<<<(M * DI) / 256, 256>>>(xz, conv_w, conv_b, xc, xch, xcl);
    // 3) dbc = xc @ W_xproj (mma, padded N=128, split-K x4)
    {
        dim3 grid(1, M / 128, KSPLIT);
        mma_gemm_k<<<grid, 256, SMEM_MMA>>>(xch, xcl, wxh, wxl, dbcpart, DI,
                                            DBC_LD, DI / KSPLIT,
                                            (size_t)M * DBC_LD);
        reduce_part_k<<<(M * DBC_LD / 4 + 255) / 256, 256>>>(
            dbcpart, dbcp, M * DBC_LD / 4, (size_t)M * DBC_LD / 4);
    }
    // 4) delta = softplus(dt_lo @ W_dt + b_dt) (SIMT, K=64)
    {
        dim3 grid(DI / 128, M / 128);
        gemm_k<128, 128, 8, 8, 8, 1><<<grid, 256>>>(dbcp, DBC_LD, W_dt, DI,
                                                    delta, DI, DR, b_dt);
    }
    // 5) parallel selective scan
    scan1_k<<<(NCH * NC) / 16, 256>>>(delta, xc, dbcp, A_log, yz, hend, ptot);
    combine_k<<<(NCH * DS) / 256, 256>>>(hend, ptot, hin);
    scan2_k<<<(NCH * NC) / 16, 256>>>(delta, xc, dbcp, xz, A_log, D_skip, hin,
                                      yz, yzh, yzl);
    // 6) out = yz @ W_out
    {
        dim3 grid(DM / 128, M / 128, 1);
        mma_gemm_k<<<grid, 256, SMEM_MMA>>>(yzh, yzl, wouth, woutl, out, DI, DM,
                                            DI, 0);
    }
}

// round 10
// speedup vs baseline: 2.2318x; 1.4566x over previous
#include <cuda_runtime.h>
#include <cuda_bf16.h>
#include <math.h>
#include <stdint.h>

// Problem constants
constexpr int Bsz = 2, Lsz = 2048, DM = 1024, DI = 2048, DS = 16, DR = 64;
constexpr int M = Bsz * Lsz;          // 4096
constexpr int XZ_N = 2 * DI;          // 4096
constexpr int DBC_LD = 128;           // padded dbc row stride (real cols: 96)
constexpr int NC = 64, LC = 32;       // scan chunking: 64 chunks x 32 steps
constexpr int NCH = Bsz * DI;         // 4096 channels
constexpr int KSPLIT = 4;             // split-K factor for dbc GEMM

// fp32 scratch
__device__ float g_xz[(size_t)M * XZ_N];
__device__ float g_xc[(size_t)M * DI];
__device__ float g_dbcp[(size_t)M * DBC_LD];
__device__ float g_dbcpart[(size_t)KSPLIT * M * DBC_LD];
__device__ float g_delta[(size_t)M * DI];
__device__ float g_yz[(size_t)M * DI];           // raw local scan y
// scan chunk state
__device__ float g_hend[(size_t)NC * NCH * DS];
__device__ float g_ptot[(size_t)NC * NCH * DS];
__device__ float g_hin [(size_t)NC * NCH * DS];
// bf16 split operands (A row-major [rows,K]; B stored K-major as [N,K])
__device__ __nv_bfloat16 g_xh[(size_t)M * DM],      g_xl[(size_t)M * DM];
__device__ __nv_bfloat16 g_winh[(size_t)XZ_N * DM], g_winl[(size_t)XZ_N * DM];
__device__ __nv_bfloat16 g_xch[(size_t)M * DI],     g_xcl[(size_t)M * DI];
__device__ __nv_bfloat16 g_wxh[(size_t)DBC_LD * DI], g_wxl[(size_t)DBC_LD * DI];
__device__ __nv_bfloat16 g_yzh[(size_t)M * DI],     g_yzl[(size_t)M * DI];
__device__ __nv_bfloat16 g_wouth[(size_t)DM * DI],  g_woutl[(size_t)DM * DI];

__device__ __forceinline__ float sigmoidf_fast(float x) {
    return 1.0f / (1.0f + __expf(-x));
}
__device__ __forceinline__ float softplusf(float x) {
    return (x > 20.0f) ? x : log1pf(expf(x));
}

// ---------------------------------------------------------------------------
// PTX helpers (portable sm_80+ PTX only)
// ---------------------------------------------------------------------------
__device__ __forceinline__ void cp_async16(uint32_t dst, const void* src) {
    asm volatile("cp.async.cg.shared.global [%0], [%1], 16;"
                 :: "r"(dst), "l"(src) : "memory");
}
__device__ __forceinline__ void cp_commit() {
    asm volatile("cp.async.commit_group;" ::: "memory");
}
template <int N>
__device__ __forceinline__ void cp_wait() {
    asm volatile("cp.async.wait_group %0;" :: "n"(N) : "memory");
}
__device__ __forceinline__ void ldsm_x4(uint32_t* r, uint32_t addr) {
    asm volatile("ldmatrix.sync.aligned.m8n8.x4.shared.b16 {%0,%1,%2,%3}, [%4];"
                 : "=r"(r[0]), "=r"(r[1]), "=r"(r[2]), "=r"(r[3]) : "r"(addr));
}
__device__ __forceinline__ void mma16816(float* c, const uint32_t* a,
                                         uint32_t b0, uint32_t b1) {
    asm volatile(
        "mma.sync.aligned.m16n8k16.row.col.f32.bf16.bf16.f32 "
        "{%0,%1,%2,%3}, {%4,%5,%6,%7}, {%8,%9}, {%0,%1,%2,%3};"
        : "+f"(c[0]), "+f"(c[1]), "+f"(c[2]), "+f"(c[3])
        : "r"(a[0]), "r"(a[1]), "r"(a[2]), "r"(a[3]), "r"(b0), "r"(b1));
}

// ---------------------------------------------------------------------------
// Split fp32 -> (hi, lo) bf16, same layout
// ---------------------------------------------------------------------------
__global__ void split_k(const float* __restrict__ in,
                        __nv_bfloat16* __restrict__ hi,
                        __nv_bfloat16* __restrict__ lo, int n4)
{
    int i = blockIdx.x * blockDim.x + threadIdx.x;
    if (i >= n4) return;
    float4 v = ((const float4*)in)[i];
    __nv_bfloat16 h0 = __float2bfloat16(v.x);
    __nv_bfloat16 h1 = __float2bfloat16(v.y);
    __nv_bfloat16 h2 = __float2bfloat16(v.z);
    __nv_bfloat16 h3 = __float2bfloat16(v.w);
    ushort4 hh, ll;
    hh.x = __bfloat16_as_ushort(h0); hh.y = __bfloat16_as_ushort(h1);
    hh.z = __bfloat16_as_ushort(h2); hh.w = __bfloat16_as_ushort(h3);
    ll.x = __bfloat16_as_ushort(__float2bfloat16(v.x - __bfloat162float(h0)));
    ll.y = __bfloat16_as_ushort(__float2bfloat16(v.y - __bfloat162float(h1)));
    ll.z = __bfloat16_as_ushort(__float2bfloat16(v.z - __bfloat162float(h2)));
    ll.w = __bfloat16_as_ushort(__float2bfloat16(v.w - __bfloat162float(h3)));
    ((ushort4*)hi)[i] = hh;
    ((ushort4*)lo)[i] = ll;
}

// ---------------------------------------------------------------------------
// Transpose + split: in [K,N] fp32 row-major -> hi/lo [N,K] bf16
// ---------------------------------------------------------------------------
__global__ void tsplit_k(const float* __restrict__ in, int Kdim, int Ndim,
                         __nv_bfloat16* __restrict__ hi,
                         __nv_bfloat16* __restrict__ lo)
{
    __shared__ float t[32][33];
    const int n0 = blockIdx.x * 32, k0 = blockIdx.y * 32;
    const int tx = threadIdx.x, ty = threadIdx.y;  // block (32, 8)
    for (int i = ty; i < 32; i += 8)
        t[i][tx] = in[(size_t)(k0 + i) * Ndim + n0 + tx];
    __syncthreads();
    for (int i = ty; i < 32; i += 8) {
        float v = t[tx][i];  // = in[k0+tx][n0+i]
        __nv_bfloat16 h = __float2bfloat16(v);
        hi[(size_t)(n0 + i) * Kdim + k0 + tx] = h;
        lo[(size_t)(n0 + i) * Kdim + k0 + tx] =
            __float2bfloat16(v - __bfloat162float(h));
    }
}

__global__ void padzero_k(__nv_bfloat16* __restrict__ a,
                          __nv_bfloat16* __restrict__ b, int n)
{
    int i = blockIdx.x * blockDim.x + threadIdx.x;
    if (i < n) { a[i] = __float2bfloat16(0.0f); b[i] = __float2bfloat16(0.0f); }
}

// Reduce KSPLIT partial C buffers into one (float4 vectorized)
__global__ void reduce_part_k(const float* __restrict__ part,
                              float* __restrict__ out, int n4, size_t zstride4)
{
    int i = blockIdx.x * blockDim.x + threadIdx.x;
    if (i >= n4) return;
    float4 a = ((const float4*)part)[i];
#pragma unroll
    for (int z = 1; z < KSPLIT; z++) {
        float4 b = ((const float4*)part)[(size_t)z * zstride4 + i];
        a.x += b.x; a.y += b.y; a.z += b.z; a.w += b.w;
    }
    ((float4*)out)[i] = a;
}

// ---------------------------------------------------------------------------
// mma.sync split-bf16 GEMM (round-9 winning config, unchanged)
// ---------------------------------------------------------------------------
constexpr int BK = 32;
constexpr int ROWB = 80;
constexpr int TILEB = 128 * ROWB;
constexpr int STAGEB = 4 * TILEB;
constexpr int NSTAGE = 3;
constexpr int SMEM_MMA = NSTAGE * STAGEB;  // 122880 B

__global__ void __launch_bounds__(256, 1) mma_gemm_k(
    const __nv_bfloat16* __restrict__ Ah, const __nv_bfloat16* __restrict__ Al,
    const __nv_bfloat16* __restrict__ Bh, const __nv_bfloat16* __restrict__ Bl,
    float* __restrict__ C, int lda, int ldc, int kspan, size_t zstride)
{
    extern __shared__ __align__(16) char smem[];
    const uint32_t sb = (uint32_t)__cvta_generic_to_shared(smem);
    const int tid = threadIdx.x;
    const int wid = tid >> 5, lid = tid & 31;
    const int warpM = wid & 3, warpN = wid >> 2;   // 4 x 2

    const int rowBase = blockIdx.y * 128;
    const int colBase = blockIdx.x * 128;
    const int kstart = blockIdx.z * kspan;
    const int nch = kspan / BK;
    C += (size_t)blockIdx.z * zstride;

    float acc[2][8][4];
#pragma unroll
    for (int i = 0; i < 2; i++)
#pragma unroll
        for (int j = 0; j < 8; j++)
#pragma unroll
            for (int q = 0; q < 4; q++) acc[i][j][q] = 0.0f;

    auto load_chunk = [&](int c, int buf) {
        const uint32_t st = sb + buf * STAGEB;
        const int k0 = kstart + c * BK;
#pragma unroll
        for (int ch = tid; ch < 512; ch += 256) {
            const int row = ch >> 2;
            const int kc = ch & 3;
            const uint32_t so = row * ROWB + kc * 16;
            const size_t go = (size_t)k0 + kc * 8;
            cp_async16(st + so,             Ah + (size_t)(rowBase + row) * lda + go);
            cp_async16(st + TILEB + so,     Al + (size_t)(rowBase + row) * lda + go);
            cp_async16(st + 2 * TILEB + so, Bh + (size_t)(colBase + row) * lda + go);
            cp_async16(st + 3 * TILEB + so, Bl + (size_t)(colBase + row) * lda + go);
        }
        cp_commit();
    };

    load_chunk(0, 0);
    load_chunk(1, 1);
    load_chunk(2, 2);

    const int lr = lid & 15;
    const int lc16 = (lid >> 4) * 16;

    for (int c = 0; c < nch; c++) {
        const int buf = c % NSTAGE;
        cp_wait<NSTAGE - 1>();
        __syncthreads();

        const uint32_t st = sb + buf * STAGEB;
#pragma unroll
        for (int kk = 0; kk < 2; kk++) {
            const uint32_t kb = kk * 32;
            uint32_t ah[2][4], al[2][4];
#pragma unroll
            for (int mf = 0; mf < 2; mf++) {
                const uint32_t a =
                    st + (warpM * 32 + mf * 16 + lr) * ROWB + kb + lc16;
                ldsm_x4(ah[mf], a);
                ldsm_x4(al[mf], a + TILEB);
            }
            uint32_t bh[8][2], bl[8][2];
#pragma unroll
            for (int np = 0; np < 4; np++) {
                const uint32_t a =
                    st + 2 * TILEB + (warpN * 64 + np * 16 + lr) * ROWB + kb + lc16;
                uint32_t t[4];
                ldsm_x4(t, a);
                bh[2 * np][0] = t[0]; bh[2 * np + 1][0] = t[1];
                bh[2 * np][1] = t[2]; bh[2 * np + 1][1] = t[3];
                ldsm_x4(t, a + TILEB);
                bl[2 * np][0] = t[0]; bl[2 * np + 1][0] = t[1];
                bl[2 * np][1] = t[2]; bl[2 * np + 1][1] = t[3];
            }
            // interleaved MMA order (proven fastest)
#pragma unroll
            for (int mf = 0; mf < 2; mf++)
#pragma unroll
                for (int nf = 0; nf < 8; nf++) {
                    mma16816(acc[mf][nf], ah[mf], bh[nf][0], bh[nf][1]);
                    mma16816(acc[mf][nf], ah[mf], bl[nf][0], bl[nf][1]);
                    mma16816(acc[mf][nf], al[mf], bh[nf][0], bh[nf][1]);
                }
        }
        __syncthreads();
        if (c + NSTAGE < nch) load_chunk(c + NSTAGE, buf);
        else cp_commit();
    }

    const int r = lid >> 2, cq = (lid & 3) * 2;
    float* Cw = C + (size_t)(rowBase + warpM * 32) * ldc + colBase + warpN * 64;
#pragma unroll
    for (int mf = 0; mf < 2; mf++)
#pragma unroll
        for (int nf = 0; nf < 8; nf++) {
            float2 v0 = make_float2(acc[mf][nf][0], acc[mf][nf][1]);
            float2 v1 = make_float2(acc[mf][nf][2], acc[mf][nf][3]);
            *(float2*)&Cw[(size_t)(mf * 16 + r) * ldc + nf * 8 + cq] = v0;
            *(float2*)&Cw[(size_t)(mf * 16 + r + 8) * ldc + nf * 8 + cq] = v1;
        }
}

// ---------------------------------------------------------------------------
// SIMT GEMM (delta). EPI: 0 none, 1 softplus(x + bias[col])
// ---------------------------------------------------------------------------
template <int BM, int BN, int BKt, int TM, int TN, int EPI>
__global__ void __launch_bounds__((BM / TM) * (BN / TN))
gemm_k(const float* __restrict__ A, int lda,
       const float* __restrict__ B, int ldb,
       float* __restrict__ C, int ldc,
       int Kdim, const float* __restrict__ bias)
{
    constexpr int THREADS = (BM / TM) * (BN / TN);
    __shared__ __align__(16) float As[BKt][BM];
    __shared__ __align__(16) float Bs[BKt][BN];

    const int tid = threadIdx.x;
    const int blockRow = blockIdx.y * BM;
    const int blockCol = blockIdx.x * BN;
    const int tRow = (tid / (BN / TN)) * TM;
    const int tCol = (tid % (BN / TN)) * TN;

    float acc[TM][TN];
#pragma unroll
    for (int i = 0; i < TM; i++)
#pragma unroll
        for (int j = 0; j < TN; j++) acc[i][j] = 0.0f;

    constexpr int A_F4_PER_ROW = BKt / 4;
    const int aRow = tid / A_F4_PER_ROW;
    const int aK = (tid % A_F4_PER_ROW) * 4;
    constexpr int A_ROWS_PER_PASS = THREADS / A_F4_PER_ROW;
    constexpr int B_F4_PER_ROW = BN / 4;
    const int bRow = tid / B_F4_PER_ROW;
    const int bCol = (tid % B_F4_PER_ROW) * 4;
    constexpr int B_ROWS_PER_PASS = THREADS / B_F4_PER_ROW;

    for (int k0 = 0; k0 < Kdim; k0 += BKt) {
#pragma unroll 1
        for (int rr = aRow; rr < BM; rr += A_ROWS_PER_PASS) {
            float4 v = *(const float4*)&A[(size_t)(blockRow + rr) * lda + k0 + aK];
            As[aK + 0][rr] = v.x; As[aK + 1][rr] = v.y;
            As[aK + 2][rr] = v.z; As[aK + 3][rr] = v.w;
        }
#pragma unroll 1
        for (int rr = bRow; rr < BKt; rr += B_ROWS_PER_PASS) {
            *(float4*)&Bs[rr][bCol] =
                *(const float4*)&B[(size_t)(k0 + rr) * ldb + blockCol + bCol];
        }
        __syncthreads();

#pragma unroll
        for (int kk = 0; kk < BKt; kk++) {
            float a[TM], bf[TN];
#pragma unroll
            for (int i = 0; i < TM; i += 4) {
                float4 v = *(const float4*)&As[kk][tRow + i];
                a[i] = v.x; a[i + 1] = v.y; a[i + 2] = v.z; a[i + 3] = v.w;
            }
#pragma unroll
            for (int j = 0; j < TN; j += 4) {
                float4 v = *(const float4*)&Bs[kk][tCol + j];
                bf[j] = v.x; bf[j + 1] = v.y; bf[j + 2] = v.z; bf[j + 3] = v.w;
            }
#pragma unroll
            for (int i = 0; i < TM; i++)
#pragma unroll
                for (int j = 0; j < TN; j++)
                    acc[i][j] = fmaf(a[i], bf[j], acc[i][j]);
        }
        __syncthreads();
    }

#pragma unroll
    for (int i = 0; i < TM; i++) {
        const int rr = blockRow + tRow + i;
#pragma unroll
        for (int j = 0; j < TN; j += 4) {
            const int cc = blockCol + tCol + j;
            float4 v;
            float v0 = acc[i][j + 0], v1 = acc[i][j + 1],
                  v2 = acc[i][j + 2], v3 = acc[i][j + 3];
            if (EPI == 1) {
                v0 = softplusf(v0 + bias[cc + 0]);
                v1 = softplusf(v1 + bias[cc + 1]);
                v2 = softplusf(v2 + bias[cc + 2]);
                v3 = softplusf(v3 + bias[cc + 3]);
            }
            v.x = v0; v.y = v1; v.z = v2; v.w = v3;
            *(float4*)&C[(size_t)rr * ldc + cc] = v;
        }
    }
}

// ---------------------------------------------------------------------------
// Depthwise causal conv (width 4) + SiLU + fused bf16 split output
// ---------------------------------------------------------------------------
__global__ void conv_silu_k(const float* __restrict__ xz,
                            const float* __restrict__ w,
                            const float* __restrict__ bias,
                            float* __restrict__ xc,
                            __nv_bfloat16* __restrict__ xch,
                            __nv_bfloat16* __restrict__ xcl)
{
    const int idx = blockIdx.x * blockDim.x + threadIdx.x;
    if (idx >= M * DI) return;
    const int d = idx % DI;
    const int m = idx / DI;
    const int l = m % Lsz;

    float acc = bias[d];
    const float w0 = w[d * 4 + 0], w1 = w[d * 4 + 1],
                w2 = w[d * 4 + 2], w3 = w[d * 4 + 3];
    if (l >= 3) acc = fmaf(w0, xz[(size_t)(m - 3) * XZ_N + d], acc);
    if (l >= 2) acc = fmaf(w1, xz[(size_t)(m - 2) * XZ_N + d], acc);
    if (l >= 1) acc = fmaf(w2, xz[(size_t)(m - 1) * XZ_N + d], acc);
    acc = fmaf(w3, xz[(size_t)m * XZ_N + d], acc);
    const float v = acc * sigmoidf_fast(acc);
    xc[idx] = v;
    const __nv_bfloat16 h = __float2bfloat16(v);
    xch[idx] = h;
    xcl[idx] = __float2bfloat16(v - __bfloat162float(h));
}

// ---------------------------------------------------------------------------
// Parallel selective scan, register-state version.
// One thread per (channel, chunk); all DS=16 states in registers.
// Block = 256 channels sharing one (batch, chunk): same m-sequence, so B/C
// rows for the whole chunk are staged in smem once and read as broadcasts.
// Grid: Bsz * (DI/256) * NC = 2*8*64 = 1024 blocks.
// ---------------------------------------------------------------------------
__global__ void __launch_bounds__(256) scan1_k(
    const float* __restrict__ delta_, const float* __restrict__ xc,
    const float* __restrict__ dbcp, const float* __restrict__ A_log,
    float* __restrict__ yz, float* __restrict__ hend, float* __restrict__ ptot)
{
    __shared__ float sB[LC][DS];
    __shared__ float sC[LC][DS];
    const int tid = threadIdx.x;
    const int blk = blockIdx.x;
    const int c = blk & (NC - 1);
    const int t = blk >> 6;            // 0..15
    const int b = t >> 3;
    const int d = ((t & 7) << 8) + tid;
    const size_t mbase = (size_t)b * Lsz + c * LC;

    // stage B/C rows for this chunk: LC*32 floats
    for (int i = tid; i < LC * 32; i += 256) {
        const int row = i >> 5, col = i & 31;
        const float v = dbcp[(mbase + row) * DBC_LD + DR + col];
        if (col < DS) sB[row][col] = v;
        else          sC[row][col - DS] = v;
    }
    float Aneg[DS];
#pragma unroll
    for (int s = 0; s < DS; s++) Aneg[s] = -__expf(A_log[d * DS + s]);
    __syncthreads();

    float h[DS], p[DS];
#pragma unroll
    for (int s = 0; s < DS; s++) { h[s] = 0.0f; p[s] = 1.0f; }

#pragma unroll 2
    for (int k = 0; k < LC; k++) {
        const size_t m = mbase + k;
        const float delta = delta_[m * DI + d];
        const float du = delta * xc[m * DI + d];
        float y = 0.0f;
#pragma unroll
        for (int s = 0; s < DS; s++) {
            const float a = __expf(delta * Aneg[s]);
            p[s] *= a;
            h[s] = fmaf(a, h[s], du * sB[k][s]);
            y = fmaf(h[s], sC[k][s], y);
        }
        yz[m * DI + d] = y;
    }
    const size_t idx = (size_t)c * (NCH * DS) + ((size_t)(b * DI + d)) * DS;
#pragma unroll
    for (int s = 0; s < DS; s++) { hend[idx + s] = h[s]; ptot[idx + s] = p[s]; }
}

__global__ void __launch_bounds__(256) combine_k(
    const float* __restrict__ hend, const float* __restrict__ ptot,
    float* __restrict__ hin)
{
    const int i = blockIdx.x * 256 + threadIdx.x;  // NCH*DS = 65536
    float H = 0.0f;
#pragma unroll
    for (int c = 0; c < NC; c++) {
        const size_t idx = (size_t)c * (NCH * DS) + i;
        hin[idx] = H;
        H = fmaf(ptot[idx], H, hend[idx]);
    }
}

__global__ void __launch_bounds__(256) scan2_k(
    const float* __restrict__ delta_, const float* __restrict__ xc,
    const float* __restrict__ dbcp, const float* __restrict__ xz,
    const float* __restrict__ A_log, const float* __restrict__ D_skip,
    const float* __restrict__ hin_, const float* __restrict__ yz,
    __nv_bfloat16* __restrict__ yzh, __nv_bfloat16* __restrict__ yzl)
{
    __shared__ float sC[LC][DS];
    const int tid = threadIdx.x;
    const int blk = blockIdx.x;
    const int c = blk & (NC - 1);
    const int t = blk >> 6;
    const int b = t >> 3;
    const int d = ((t & 7) << 8) + tid;
    const size_t mbase = (size_t)b * Lsz + c * LC;

    for (int i = tid; i < LC * DS; i += 256) {
        const int row = i >> 4, col = i & 15;
        sC[row][col] = dbcp[(mbase + row) * DBC_LD + DR + DS + col];
    }
    float Aneg[DS];
#pragma unroll
    for (int s = 0; s < DS; s++) Aneg[s] = -__expf(A_log[d * DS + s]);
    const float dskip = D_skip[d];

    float hin[DS], p[DS];
    const size_t hidx = (size_t)c * (NCH * DS) + ((size_t)(b * DI + d)) * DS;
#pragma unroll
    for (int s = 0; s < DS; s++) { hin[s] = hin_[hidx + s]; p[s] = 1.0f; }
    __syncthreads();

#pragma unroll 2
    for (int k = 0; k < LC; k++) {
        const size_t m = mbase + k;
        const float delta = delta_[m * DI + d];
        float yc = 0.0f;
#pragma unroll
        for (int s = 0; s < DS; s++) {
            const float a = __expf(delta * Aneg[s]);
            p[s] *= a;
            yc = fmaf(hin[s] * p[s], sC[k][s], yc);
        }
        const float u = xc[m * DI + d];
        const float z = xz[m * XZ_N + DI + d];
        const float y = yz[m * DI + d] + yc + u * dskip;
        const float val = y * (z * sigmoidf_fast(z));
        const __nv_bfloat16 hh = __float2bfloat16(val);
        yzh[m * DI + d] = hh;
        yzl[m * DI + d] = __float2bfloat16(val - __bfloat162float(hh));
    }
}

// ---------------------------------------------------------------------------
extern "C" void kernel_launch(void* const* d_in, const int* in_sizes, int n_in,
                              void* d_out, int out_size)
{
    const float* x      = (const float*)d_in[0];
    const float* W_in   = (const float*)d_in[1];
    const float* conv_w = (const float*)d_in[2];
    const float* conv_b = (const float*)d_in[3];
    const float* W_xprj = (const float*)d_in[4];
    const float* W_dt   = (const float*)d_in[5];
    const float* b_dt   = (const float*)d_in[6];
    const float* A_log  = (const float*)d_in[7];
    const float* D_skip = (const float*)d_in[8];
    const float* W_out  = (const float*)d_in[9];
    float* out = (float*)d_out;

    float *xz, *xc, *dbcp, *dbcpart, *delta, *yz, *hend, *ptot, *hin;
    cudaGetSymbolAddress((void**)&xz, g_xz);
    cudaGetSymbolAddress((void**)&xc, g_xc);
    cudaGetSymbolAddress((void**)&dbcp, g_dbcp);
    cudaGetSymbolAddress((void**)&dbcpart, g_dbcpart);
    cudaGetSymbolAddress((void**)&delta, g_delta);
    cudaGetSymbolAddress((void**)&yz, g_yz);
    cudaGetSymbolAddress((void**)&hend, g_hend);
    cudaGetSymbolAddress((void**)&ptot, g_ptot);
    cudaGetSymbolAddress((void**)&hin, g_hin);
    __nv_bfloat16 *xh, *xl, *winh, *winl, *xch, *xcl, *wxh, *wxl,
                  *yzh, *yzl, *wouth, *woutl;
    cudaGetSymbolAddress((void**)&xh, g_xh);
    cudaGetSymbolAddress((void**)&xl, g_xl);
    cudaGetSymbolAddress((void**)&winh, g_winh);
    cudaGetSymbolAddress((void**)&winl, g_winl);
    cudaGetSymbolAddress((void**)&xch, g_xch);
    cudaGetSymbolAddress((void**)&xcl, g_xcl);
    cudaGetSymbolAddress((void**)&wxh, g_wxh);
    cudaGetSymbolAddress((void**)&wxl, g_wxl);
    cudaGetSymbolAddress((void**)&yzh, g_yzh);
    cudaGetSymbolAddress((void**)&yzl, g_yzl);
    cudaGetSymbolAddress((void**)&wouth, g_wouth);
    cudaGetSymbolAddress((void**)&woutl, g_woutl);

    cudaFuncSetAttribute(mma_gemm_k, cudaFuncAttributeMaxDynamicSharedMemorySize,
                         SMEM_MMA);

    // 0) operand prep
    split_k<<<(M * DM / 4 + 255) / 256, 256>>>(x, xh, xl, M * DM / 4);
    {   // W_in [DM, XZ_N] -> [XZ_N, DM]
        dim3 grid(XZ_N / 32, DM / 32);
        tsplit_k<<<grid, dim3(32, 8)>>>(W_in, DM, XZ_N, winh, winl);
    }
    {   // W_out [DI, DM] -> [DM, DI]
        dim3 grid(DM / 32, DI / 32);
        tsplit_k<<<grid, dim3(32, 8)>>>(W_out, DI, DM, wouth, woutl);
    }
    {   // W_xproj [DI, 96] -> [96, DI], pad rows 96..127 with zeros
        dim3 grid(96 / 32, DI / 32);
        tsplit_k<<<grid, dim3(32, 8)>>>(W_xprj, DI, 96, wxh, wxl);
        padzero_k<<<(32 * DI + 255) / 256, 256>>>(wxh + (size_t)96 * DI,
                                                  wxl + (size_t)96 * DI, 32 * DI);
    }

    // 1) xz = x @ W_in
    {
        dim3 grid(XZ_N / 128, M / 128, 1);
        mma_gemm_k<<<grid, 256, SMEM_MMA>>>(xh, xl, winh, winl, xz, DM, XZ_N,
                                            DM, 0);
    }
    // 2) conv + silu (+ bf16 split)
    conv_silu_k<<<(M * DI) / 256, 256>>>(xz, conv_w, conv_b, xc, xch, xcl);
    // 3) dbc = xc @ W_xproj (mma, padded N=128, split-K x4)
    {
        dim3 grid(1, M / 128, KSPLIT);
        mma_gemm_k<<<grid, 256, SMEM_MMA>>>(xch, xcl, wxh, wxl, dbcpart, DI,
                                            DBC_LD, DI / KSPLIT,
                                            (size_t)M * DBC_LD);
        reduce_part_k<<<(M * DBC_LD / 4 + 255) / 256, 256>>>(
            dbcpart, dbcp, M * DBC_LD / 4, (size_t)M * DBC_LD / 4);
    }
    // 4) delta = softplus(dt_lo @ W_dt + b_dt) (SIMT, K=64)
    {
        dim3 grid(DI / 128, M / 128);
        gemm_k<128, 128, 8, 8, 8, 1><<<grid, 256>>>(dbcp, DBC_LD, W_dt, DI,
                                                    delta, DI, DR, b_dt);
    }
    // 5) parallel selective scan (register-state version)
    {
        const int blocks = Bsz * (DI / 256) * NC;  // 1024
        scan1_k<<<blocks, 256>>>(delta, xc, dbcp, A_log, yz, hend, ptot);
        combine_k<<<(NCH * DS) / 256, 256>>>(hend, ptot, hin);
        scan2_k<<<blocks, 256>>>(delta, xc, dbcp, xz, A_log, D_skip, hin,
                                 yz, yzh, yzl);
    }
    // 6) out = yz @ W_out
    {
        dim3 grid(DM / 128, M / 128, 1);
        mma_gemm_k<<<grid, 256, SMEM_MMA>>>(yzh, yzl, wouth, woutl, out, DI, DM,
                                            DI, 0);
    }
}